// round 2
// baseline (speedup 1.0000x reference)
#include <cuda_runtime.h>
#include <math.h>

// Problem constants
#define B_    8
#define S_    64
#define T_    512
#define HID_  4096
#define NH_   32
#define NKV_  32
#define D_    128
#define HIST_ 2048
#define BSZ_  64
#define NBLK_ 33
#define L_    2112
#define QKVW  12288   // 3 * HID_

// Scratch (device globals: allocation-guard safe)
__device__ float g_qkv[(size_t)T_ * QKVW];    // [T][q(4096) | k(4096) | v(4096)]
__device__ float g_attn[(size_t)T_ * HID_];   // attention output, pre-Wo

// ------------------------------------------------------------------
// SGEMM: C[M,Ntot] = A[M,K] @ Bsel[K,Nper], 128x128x8 tile, 256 thr,
// 8x8 per-thread microtile. B operand selected per n-block from up to
// three weight matrices laid side by side (fused QKV projection).
// ------------------------------------------------------------------
#define BM 128
#define BN 128
#define BK 8

__global__ __launch_bounds__(256) void sgemm_k(
    const float* __restrict__ A,
    const float* __restrict__ B0, const float* __restrict__ B1,
    const float* __restrict__ B2,
    float* __restrict__ C, int K, int Nper, int Ntot)
{
    __shared__ float As[BK][BM];
    __shared__ float Bs[BK][BN];

    int tid = threadIdx.x;
    int bx = blockIdx.x, by = blockIdx.y;
    int n0 = bx * BN;

    const float* Bp; int nloc;
    if (n0 < Nper)           { Bp = B0; nloc = n0; }
    else if (n0 < 2 * Nper)  { Bp = B1; nloc = n0 - Nper; }
    else                     { Bp = B2; nloc = n0 - 2 * Nper; }

    int tx = tid & 15, ty = tid >> 4;

    int aRow = tid >> 1;           // 0..127
    int aCol = (tid & 1) << 2;     // 0 or 4
    int bRow = tid >> 5;           // 0..7
    int bCol = (tid & 31) << 2;    // 0..124

    const float* Ap = A + (size_t)(by * BM + aRow) * K + aCol;
    const float* Bq = Bp + (size_t)bRow * Nper + nloc + bCol;

    float acc[8][8];
#pragma unroll
    for (int i = 0; i < 8; i++)
#pragma unroll
        for (int j = 0; j < 8; j++) acc[i][j] = 0.f;

    for (int k0 = 0; k0 < K; k0 += BK) {
        float4 av = *(const float4*)(Ap + k0);
        As[aCol + 0][aRow] = av.x;
        As[aCol + 1][aRow] = av.y;
        As[aCol + 2][aRow] = av.z;
        As[aCol + 3][aRow] = av.w;
        float4 bv = *(const float4*)(Bq + (size_t)k0 * Nper);
        *(float4*)&Bs[bRow][bCol] = bv;
        __syncthreads();

#pragma unroll
        for (int kk = 0; kk < BK; kk++) {
            float ar[8], br[8];
            *(float4*)(ar)     = *(const float4*)&As[kk][ty * 8];
            *(float4*)(ar + 4) = *(const float4*)&As[kk][ty * 8 + 4];
            *(float4*)(br)     = *(const float4*)&Bs[kk][tx * 8];
            *(float4*)(br + 4) = *(const float4*)&Bs[kk][tx * 8 + 4];
#pragma unroll
            for (int i = 0; i < 8; i++)
#pragma unroll
                for (int j = 0; j < 8; j++)
                    acc[i][j] += ar[i] * br[j];
        }
        __syncthreads();
    }

#pragma unroll
    for (int i = 0; i < 8; i++) {
        int row = by * BM + ty * 8 + i;
        float* cp = C + (size_t)row * Ntot + n0 + tx * 8;
        float4 v0 = make_float4(acc[i][0], acc[i][1], acc[i][2], acc[i][3]);
        float4 v1 = make_float4(acc[i][4], acc[i][5], acc[i][6], acc[i][7]);
        *(float4*)(cp)     = v0;
        *(float4*)(cp + 4) = v1;
    }
}

// ------------------------------------------------------------------
// RoPE applied in place on q (cols [0,4096)) and k (cols [4096,8192))
// of g_qkv. One thread per (token, head, rot-pair). h in [0,64):
// h<32 -> q head h; h>=32 -> k head h-32 (col = h*128 + i directly).
// ------------------------------------------------------------------
__global__ __launch_bounds__(256) void rope_k(const int* __restrict__ pos_ids)
{
    int idx = blockIdx.x * 256 + threadIdx.x;          // T_*64*64 threads
    int i = idx & 63;
    int h = (idx >> 6) & 63;
    int t = idx >> 12;
    if (t >= T_) return;

    float p = (float)pos_ids[t];
    float inv = expf((float)i * (-9.210340371976184f / 64.0f)); // 10000^(-i/64)
    float ang = p * inv;
    float s, c;
    sincosf(ang, &s, &c);

    size_t base = (size_t)t * QKVW + (size_t)h * D_ + i;
    float x0 = g_qkv[base];
    float x1 = g_qkv[base + 64];
    g_qkv[base]      = x0 * c - x1 * s;
    g_qkv[base + 64] = x1 * c + x0 * s;
}

// ------------------------------------------------------------------
// Flash attention. One CTA per (head n, sequence b). 256 threads.
// 64 queries x 128 dims in smem; stream 33 tiles of 64 keys (tiles
// 0..31 from the paged cache, tile 32 = the freshly-projected K/V).
// Online softmax; O accumulator in registers (32 floats/thread).
// Smem tiles XOR-swizzled at float4 granularity.
// ------------------------------------------------------------------
__device__ __forceinline__ int sw_off(int row, int ck)
{
    return (row << 7) + (((ck ^ ((row >> 2) & 7))) << 2);
}

__global__ __launch_bounds__(256) void attn_k(
    const float* __restrict__ k_cache, const float* __restrict__ v_cache,
    const int* __restrict__ pos_ids, const int* __restrict__ block_offsets)
{
    extern __shared__ float smf[];
    float* q_s   = smf;                   // 64*128
    float* kv_s  = smf + 8192;            // 64*128 (K then V)
    float* s_s   = smf + 16384;           // 64*68
    float* row_m = smf + 16384 + 4352;    // 64
    float* row_l = row_m + 64;            // 64
    float* row_c = row_l + 64;            // 64 (per-tile rescale)
    int*   pos_s = (int*)(row_c + 64);    // 64

    int n = blockIdx.x, b = blockIdx.y;
    int tid = threadIdx.x;

    const float* qbase = g_qkv + (size_t)b * S_ * QKVW + (size_t)n * D_;
    for (int e = tid; e < 64 * 32; e += 256) {
        int r = e >> 5, ck = e & 31;
        float4 v = *(const float4*)(qbase + (size_t)r * QKVW + (ck << 2));
        *(float4*)&q_s[sw_off(r, ck)] = v;
    }
    if (tid < 64) {
        row_m[tid] = -3.0e38f;
        row_l[tid] = 0.f;
        pos_s[tid] = pos_ids[b * S_ + tid];
    }
    __syncthreads();

    int tx = tid & 15, ty = tid >> 4;      // score grid 16x16 (4x4 each)
    int r_pv = tid >> 2, q4 = tid & 3;     // PV: row + column-phase

    float4 o[8];
#pragma unroll
    for (int i = 0; i < 8; i++) o[i] = make_float4(0.f, 0.f, 0.f, 0.f);

    const float scale = 0.08838834764831845f;  // 1/sqrt(128)

    for (int t = 0; t < 33; t++) {
        // ---- load K tile ----
        const float* kbase; size_t kstride;
        if (t < 32) {
            int blk = block_offsets[b * NBLK_ + t];
            kbase = k_cache + ((size_t)blk * BSZ_ * NKV_ + n) * D_;
            kstride = (size_t)NKV_ * D_;
        } else {
            kbase = g_qkv + (size_t)b * S_ * QKVW + HID_ + (size_t)n * D_;
            kstride = QKVW;
        }
        for (int e = tid; e < 64 * 32; e += 256) {
            int w = e >> 5, ck = e & 31;
            float4 v = *(const float4*)(kbase + (size_t)w * kstride + (ck << 2));
            *(float4*)&kv_s[sw_off(w, ck)] = v;
        }
        __syncthreads();

        // ---- scores: S[64][64] = Q K^T ----
        {
            float acc[4][4];
#pragma unroll
            for (int i = 0; i < 4; i++)
#pragma unroll
                for (int j = 0; j < 4; j++) acc[i][j] = 0.f;

#pragma unroll 4
            for (int ck = 0; ck < 32; ck++) {
                float4 qv[4], kv[4];
#pragma unroll
                for (int i = 0; i < 4; i++)
                    qv[i] = *(const float4*)&q_s[sw_off(ty * 4 + i, ck)];
#pragma unroll
                for (int j = 0; j < 4; j++)
                    kv[j] = *(const float4*)&kv_s[sw_off(tx * 4 + j, ck)];
#pragma unroll
                for (int i = 0; i < 4; i++)
#pragma unroll
                    for (int j = 0; j < 4; j++)
                        acc[i][j] += qv[i].x * kv[j].x + qv[i].y * kv[j].y
                                   + qv[i].z * kv[j].z + qv[i].w * kv[j].w;
            }
#pragma unroll
            for (int i = 0; i < 4; i++)
#pragma unroll
                for (int j = 0; j < 4; j++)
                    s_s[(ty * 4 + i) * 68 + tx * 4 + j] = acc[i][j] * scale;
        }
        __syncthreads();

        // ---- online softmax (4 threads per query row) ----
        {
            int r = tid >> 2, u = tid & 3;
            int lb = t * 64;
            int pr = pos_s[r];
            float mloc = -3.0e38f;
#pragma unroll
            for (int jj = 0; jj < 16; jj++) {
                int j = u * 16 + jj;
                if (lb + j <= pr) mloc = fmaxf(mloc, s_s[r * 68 + j]);
            }
            mloc = fmaxf(mloc, __shfl_xor_sync(0xffffffffu, mloc, 1));
            mloc = fmaxf(mloc, __shfl_xor_sync(0xffffffffu, mloc, 2));
            float mnew = fmaxf(row_m[r], mloc);
            float sum = 0.f;
#pragma unroll
            for (int jj = 0; jj < 16; jj++) {
                int j = u * 16 + jj;
                float pv = 0.f;
                if (lb + j <= pr) pv = expf(s_s[r * 68 + j] - mnew);
                s_s[r * 68 + j] = pv;
                sum += pv;
            }
            sum += __shfl_xor_sync(0xffffffffu, sum, 1);
            sum += __shfl_xor_sync(0xffffffffu, sum, 2);
            if (u == 0) {
                float corr = expf(row_m[r] - mnew);
                row_c[r] = corr;
                row_l[r] = row_l[r] * corr + sum;
                row_m[r] = mnew;
            }
        }
        __syncthreads();

        // ---- load V tile (reuse kv_s) ----
        const float* vbase; size_t vstride;
        if (t < 32) {
            int blk = block_offsets[b * NBLK_ + t];
            vbase = v_cache + ((size_t)blk * BSZ_ * NKV_ + n) * D_;
            vstride = (size_t)NKV_ * D_;
        } else {
            vbase = g_qkv + (size_t)b * S_ * QKVW + 2 * HID_ + (size_t)n * D_;
            vstride = QKVW;
        }
        for (int e = tid; e < 64 * 32; e += 256) {
            int w = e >> 5, ck = e & 31;
            float4 v = *(const float4*)(vbase + (size_t)w * vstride + (ck << 2));
            *(float4*)&kv_s[sw_off(w, ck)] = v;
        }
        __syncthreads();

        // ---- O = O*corr + P @ V ----
        {
            float corr = row_c[r_pv];
#pragma unroll
            for (int i = 0; i < 8; i++) {
                o[i].x *= corr; o[i].y *= corr; o[i].z *= corr; o[i].w *= corr;
            }
#pragma unroll 2
            for (int j = 0; j < 64; j++) {
                float p = s_s[r_pv * 68 + j];
#pragma unroll
                for (int i = 0; i < 8; i++) {
                    int ck = q4 + 4 * i;
                    float4 v = *(const float4*)&kv_s[sw_off(j, ck)];
                    o[i].x += p * v.x; o[i].y += p * v.y;
                    o[i].z += p * v.z; o[i].w += p * v.w;
                }
            }
        }
        __syncthreads();   // kv_s reused as K next tile
    }

    // ---- epilogue ----
    float inv_l = 1.0f / row_l[r_pv];
    float* obase = g_attn + (size_t)(b * S_ + r_pv) * HID_ + (size_t)n * D_;
#pragma unroll
    for (int i = 0; i < 8; i++) {
        int ck = q4 + 4 * i;
        float4 v = o[i];
        v.x *= inv_l; v.y *= inv_l; v.z *= inv_l; v.w *= inv_l;
        *(float4*)(obase + (ck << 2)) = v;
    }
}

// ------------------------------------------------------------------
// Launch
// ------------------------------------------------------------------
extern "C" void kernel_launch(void* const* d_in, const int* in_sizes, int n_in,
                              void* d_out, int out_size)
{
    const float* X  = (const float*)d_in[0];
    const float* kc = (const float*)d_in[1];
    const float* vc = (const float*)d_in[2];
    const float* wq = (const float*)d_in[3];
    const float* wk = (const float*)d_in[4];
    const float* wv = (const float*)d_in[5];
    const float* wo = (const float*)d_in[6];
    const int* pos  = (const int*)d_in[7];
    const int* bo   = (const int*)d_in[8];
    float* out = (float*)d_out;

    float *qkv_p, *attn_p;
    cudaGetSymbolAddress((void**)&qkv_p, g_qkv);
    cudaGetSymbolAddress((void**)&attn_p, g_attn);

    int attn_smem = (8192 + 8192 + 64 * 68 + 4 * 64) * 4;  // 83968 B
    cudaFuncSetAttribute(attn_k, cudaFuncAttributeMaxDynamicSharedMemorySize,
                         attn_smem);

    // 1) fused QKV projection: [512,4096] @ [4096, 12288]
    dim3 g1(QKVW / BN, T_ / BM);
    sgemm_k<<<g1, 256>>>(X, wq, wk, wv, qkv_p, HID_, HID_, QKVW);

    // 2) RoPE on q and k
    rope_k<<<(T_ * 64 * 64) / 256, 256>>>(pos);

    // 3) paged causal flash attention
    attn_k<<<dim3(NH_, B_), 256, attn_smem>>>(kc, vc, pos, bo);

    // 4) output projection: [512,4096] @ [4096,4096]
    dim3 g2(HID_ / BN, T_ / BM);
    sgemm_k<<<g2, 256>>>(attn_p, wo, wo, wo, out, HID_, HID_, HID_);
}

// round 4
// speedup vs baseline: 2.1474x; 2.1474x over previous
#include <cuda_runtime.h>
#include <cuda_bf16.h>
#include <math.h>
#include <stdint.h>

// Problem constants
#define B_    8
#define S_    64
#define T_    512
#define HID_  4096
#define NH_   32
#define NKV_  32
#define D_    128
#define HIST_ 2048
#define BSZ_  64
#define NBLK_ 33
#define L_    2112
#define QKVW  12288   // 3 * HID_

// Scratch (device globals: allocation-guard safe)
__device__ float g_qkv[(size_t)T_ * QKVW];    // [T][q(4096) | k(4096) | v(4096)]
__device__ float g_attn[(size_t)T_ * HID_];   // attention output, pre-Wo

// ==================================================================
// Helpers: bf16 pack/unpack + mma.sync + ldmatrix (sm_80 features,
// valid at base sm_103 target — no 'a'-suffix required)
// ==================================================================
__device__ __forceinline__ uint32_t smem_u32(const void* p) {
    return (uint32_t)__cvta_generic_to_shared(p);
}

// pack two fp32 -> bf16x2 (x0 in low half, x1 in high half)
__device__ __forceinline__ uint32_t pack_bf2(float x0, float x1) {
    uint32_t d;
    asm("cvt.rn.bf16x2.f32 %0, %1, %2;" : "=r"(d) : "f"(x1), "f"(x0));
    return d;
}
// bf16x2 -> two fp32 (exact: bf16 is the top 16 bits of fp32)
__device__ __forceinline__ float2 unpack_bf2(uint32_t u) {
    float2 r;
    r.x = __uint_as_float(u << 16);
    r.y = __uint_as_float(u & 0xffff0000u);
    return r;
}
// split float4 into bf16 hi pairs + residual lo pairs
__device__ __forceinline__ void split4(float4 v, uint32_t* hi, uint32_t* lo) {
    uint32_t h0 = pack_bf2(v.x, v.y);
    uint32_t h1 = pack_bf2(v.z, v.w);
    float2 f0 = unpack_bf2(h0), f1 = unpack_bf2(h1);
    hi[0] = h0; hi[1] = h1;
    lo[0] = pack_bf2(v.x - f0.x, v.y - f0.y);
    lo[1] = pack_bf2(v.z - f1.x, v.w - f1.y);
}

__device__ __forceinline__ void ldsm4(uint32_t* r, uint32_t addr) {
    asm volatile("ldmatrix.sync.aligned.m8n8.x4.shared.b16 {%0,%1,%2,%3}, [%4];"
                 : "=r"(r[0]), "=r"(r[1]), "=r"(r[2]), "=r"(r[3]) : "r"(addr));
}

__device__ __forceinline__ void mma16816(float* d, const uint32_t* a, const uint32_t* b) {
    asm volatile("mma.sync.aligned.m16n8k16.row.col.f32.bf16.bf16.f32 "
                 "{%0,%1,%2,%3}, {%4,%5,%6,%7}, {%8,%9}, {%0,%1,%2,%3};"
                 : "+f"(d[0]), "+f"(d[1]), "+f"(d[2]), "+f"(d[3])
                 : "r"(a[0]), "r"(a[1]), "r"(a[2]), "r"(a[3]),
                   "r"(b[0]), "r"(b[1]));
}

// ==================================================================
// bf16x2-split GEMM on mma.sync.  C[M,Ntot] = A[M,K] @ Bsel[K,Nper].
// CTA tile 128x128, BK=32, 8 warps (2M x 4N), warp tile 64x32.
// Smem: per stage Ah|Al|Bh|Bl, each [128 rows x 32 bf16] (64B rows),
// 16B-chunk XOR swizzle: c ^= (row>>1)&3 -> conflict-free STS.128 and
// ldmatrix.  Double buffered, register prefetch of next chunk.
// ==================================================================
#define BKC 32
#define NCH (HID_ / BKC)      // 128
#define TSTAGE 8192           // one tile: 128 * 64 B
#define STAGE  (4 * TSTAGE)   // 32 KB per stage

__global__ __launch_bounds__(256, 1)
void gemm_mma(const float* __restrict__ A,
              const float* __restrict__ B0, const float* __restrict__ B1,
              const float* __restrict__ B2,
              float* __restrict__ C, int K, int Nper, int Ntot)
{
    extern __shared__ char dynsm[];
    uint32_t sraw = smem_u32(dynsm);
    char* sm = dynsm + (((sraw + 127u) & ~127u) - sraw);
    uint32_t smb = smem_u32(sm);

    int tid = threadIdx.x, lane = tid & 31, wid = tid >> 5;
    int m0 = blockIdx.y * 128, col0 = blockIdx.x * 128;

    const float* Bp; int nloc;
    if (col0 < Nper)          { Bp = B0; nloc = col0; }
    else if (col0 < 2 * Nper) { Bp = B1; nloc = col0 - Nper; }
    else                      { Bp = B2; nloc = col0 - 2 * Nper; }
    size_t NperS = (size_t)Nper;

    // ---- load-side indexing ----
    int rA = tid >> 1, halfA = tid & 1;
    const float* Aptr = A + (size_t)(m0 + rA) * K + halfA * 16;
    int nB = tid & 127, kg = tid >> 7;          // kg in {0,1}
    const float* Bptr = Bp + nloc + nB;

    int rxA = (rA >> 1) & 3;
    int sA_off0 = rA * 64 + (((halfA * 2 + 0) ^ rxA) << 4);
    int sA_off1 = rA * 64 + (((halfA * 2 + 1) ^ rxA) << 4);
    int rxB = (nB >> 1) & 3;
    int sB_off0 = nB * 64 + (((kg + 0) ^ rxB) << 4);   // k 0..15 half (c=kg)
    int sB_off1 = nB * 64 + (((kg + 2) ^ rxB) << 4);   // k 16..31 half (c=kg+2)

    // ---- mma-side (ldmatrix) indexing ----
    int wm = wid & 1, wn = wid >> 1;
    int aRow = wm * 64 + ((lane >> 3) & 1) * 8 + (lane & 7);
    int aCh  = (lane >> 4) & 1;
    int aRX  = (aRow >> 1) & 3;
    uint32_t aOff = (uint32_t)(aRow * 64);
    int nbRow = wn * 32 + ((lane >> 4) & 1) * 8 + (lane & 7);
    int bCh   = (lane >> 3) & 1;
    int bRX   = (nbRow >> 1) & 3;
    uint32_t nbOff = (uint32_t)(nbRow * 64);

    float acc[4][4][4];
#pragma unroll
    for (int i = 0; i < 4; i++)
#pragma unroll
        for (int j = 0; j < 4; j++)
#pragma unroll
            for (int e = 0; e < 4; e++) acc[i][j][e] = 0.f;

    float4 pa[4];
    float  pb[16];

    // prefetch chunk 0
    {
        const float* ap = Aptr;
#pragma unroll
        for (int q = 0; q < 4; q++) pa[q] = *(const float4*)(ap + q * 4);
        const float* bp = Bptr + (size_t)(kg * 8) * NperS;
#pragma unroll
        for (int j = 0; j < 8; j++) {
            pb[j]     = bp[(size_t)j * NperS];
            pb[8 + j] = bp[(size_t)(j + 16) * NperS];
        }
    }

    for (int c = 0; c < NCH; c++) {
        int bufOff = (c & 1) * STAGE;
        char* base = sm + bufOff;

        // ---- STS prefetched chunk c (convert fp32 -> bf16 hi/lo) ----
        {
            uint32_t h[8], l[8];
#pragma unroll
            for (int q = 0; q < 4; q++) split4(pa[q], h + 2 * q, l + 2 * q);
            *(uint4*)(base + sA_off0)          = make_uint4(h[0], h[1], h[2], h[3]);
            *(uint4*)(base + sA_off1)          = make_uint4(h[4], h[5], h[6], h[7]);
            *(uint4*)(base + TSTAGE + sA_off0) = make_uint4(l[0], l[1], l[2], l[3]);
            *(uint4*)(base + TSTAGE + sA_off1) = make_uint4(l[4], l[5], l[6], l[7]);

            uint32_t bh[4], bl[4];
#pragma unroll
            for (int q = 0; q < 4; q++) {
                bh[q] = pack_bf2(pb[2 * q], pb[2 * q + 1]);
                float2 f = unpack_bf2(bh[q]);
                bl[q] = pack_bf2(pb[2 * q] - f.x, pb[2 * q + 1] - f.y);
            }
            *(uint4*)(base + 2 * TSTAGE + sB_off0) = make_uint4(bh[0], bh[1], bh[2], bh[3]);
            *(uint4*)(base + 3 * TSTAGE + sB_off0) = make_uint4(bl[0], bl[1], bl[2], bl[3]);
#pragma unroll
            for (int q = 0; q < 4; q++) {
                bh[q] = pack_bf2(pb[8 + 2 * q], pb[9 + 2 * q]);
                float2 f = unpack_bf2(bh[q]);
                bl[q] = pack_bf2(pb[8 + 2 * q] - f.x, pb[9 + 2 * q] - f.y);
            }
            *(uint4*)(base + 2 * TSTAGE + sB_off1) = make_uint4(bh[0], bh[1], bh[2], bh[3]);
            *(uint4*)(base + 3 * TSTAGE + sB_off1) = make_uint4(bl[0], bl[1], bl[2], bl[3]);
        }
        __syncthreads();

        // ---- prefetch chunk c+1 (overlaps MMA below) ----
        if (c + 1 < NCH) {
            const float* ap = Aptr + (c + 1) * BKC;
#pragma unroll
            for (int q = 0; q < 4; q++) pa[q] = *(const float4*)(ap + q * 4);
            const float* bp = Bptr + (size_t)((c + 1) * BKC + kg * 8) * NperS;
#pragma unroll
            for (int j = 0; j < 8; j++) {
                pb[j]     = bp[(size_t)j * NperS];
                pb[8 + j] = bp[(size_t)(j + 16) * NperS];
            }
        }

        // ---- compute chunk c: 2 k16 steps ----
        uint32_t stageA = smb + bufOff;
        uint32_t stageB = smb + bufOff + 2 * TSTAGE;
#pragma unroll
        for (int s = 0; s < 2; s++) {
            uint32_t bfh[4][2], bfl[4][2];
#pragma unroll
            for (int half = 0; half < 2; half++) {
                uint32_t addr = stageB + half * 1024 + nbOff
                              + ((((s * 2) + bCh) ^ bRX) << 4);
                uint32_t r[4];
                ldsm4(r, addr);
                bfh[half * 2][0] = r[0]; bfh[half * 2][1] = r[1];
                bfh[half * 2 + 1][0] = r[2]; bfh[half * 2 + 1][1] = r[3];
                ldsm4(r, addr + TSTAGE);
                bfl[half * 2][0] = r[0]; bfl[half * 2][1] = r[1];
                bfl[half * 2 + 1][0] = r[2]; bfl[half * 2 + 1][1] = r[3];
            }
#pragma unroll
            for (int mt = 0; mt < 4; mt++) {
                uint32_t addr = stageA + mt * 1024 + aOff
                              + ((((s * 2) + aCh) ^ aRX) << 4);
                uint32_t ah[4], al[4];
                ldsm4(ah, addr);
                ldsm4(al, addr + TSTAGE);
#pragma unroll
                for (int nt = 0; nt < 4; nt++) {
                    mma16816(acc[mt][nt], ah, bfh[nt]);
                    mma16816(acc[mt][nt], ah, bfl[nt]);
                    mma16816(acc[mt][nt], al, bfh[nt]);
                }
            }
        }
        __syncthreads();
    }

    // ---- epilogue: fragment -> fp32 C ----
#pragma unroll
    for (int mt = 0; mt < 4; mt++) {
        int row = m0 + wm * 64 + mt * 16 + (lane >> 2);
#pragma unroll
        for (int nt = 0; nt < 4; nt++) {
            int col = col0 + wn * 32 + nt * 8 + (lane & 3) * 2;
            *(float2*)(C + (size_t)row * Ntot + col) =
                make_float2(acc[mt][nt][0], acc[mt][nt][1]);
            *(float2*)(C + (size_t)(row + 8) * Ntot + col) =
                make_float2(acc[mt][nt][2], acc[mt][nt][3]);
        }
    }
}

// ------------------------------------------------------------------
// RoPE applied in place on q (cols [0,4096)) and k (cols [4096,8192))
// of g_qkv. One thread per (token, head, rot-pair).
// ------------------------------------------------------------------
__global__ __launch_bounds__(256) void rope_k(const int* __restrict__ pos_ids)
{
    int idx = blockIdx.x * 256 + threadIdx.x;
    int i = idx & 63;
    int h = (idx >> 6) & 63;
    int t = idx >> 12;
    if (t >= T_) return;

    float p = (float)pos_ids[t];
    float inv = expf((float)i * (-9.210340371976184f / 64.0f));
    float ang = p * inv;
    float s, c;
    sincosf(ang, &s, &c);

    size_t base = (size_t)t * QKVW + (size_t)h * D_ + i;
    float x0 = g_qkv[base];
    float x1 = g_qkv[base + 64];
    g_qkv[base]      = x0 * c - x1 * s;
    g_qkv[base + 64] = x1 * c + x0 * s;
}

// ------------------------------------------------------------------
// Flash attention (fp32 SIMT, unchanged from passing R0 kernel).
// ------------------------------------------------------------------
__device__ __forceinline__ int sw_off(int row, int ck)
{
    return (row << 7) + (((ck ^ ((row >> 2) & 7))) << 2);
}

__global__ __launch_bounds__(256) void attn_k(
    const float* __restrict__ k_cache, const float* __restrict__ v_cache,
    const int* __restrict__ pos_ids, const int* __restrict__ block_offsets)
{
    extern __shared__ float smf[];
    float* q_s   = smf;
    float* kv_s  = smf + 8192;
    float* s_s   = smf + 16384;
    float* row_m = smf + 16384 + 4352;
    float* row_l = row_m + 64;
    float* row_c = row_l + 64;
    int*   pos_s = (int*)(row_c + 64);

    int n = blockIdx.x, b = blockIdx.y;
    int tid = threadIdx.x;

    const float* qbase = g_qkv + (size_t)b * S_ * QKVW + (size_t)n * D_;
    for (int e = tid; e < 64 * 32; e += 256) {
        int r = e >> 5, ck = e & 31;
        float4 v = *(const float4*)(qbase + (size_t)r * QKVW + (ck << 2));
        *(float4*)&q_s[sw_off(r, ck)] = v;
    }
    if (tid < 64) {
        row_m[tid] = -3.0e38f;
        row_l[tid] = 0.f;
        pos_s[tid] = pos_ids[b * S_ + tid];
    }
    __syncthreads();

    int tx = tid & 15, ty = tid >> 4;
    int r_pv = tid >> 2, q4 = tid & 3;

    float4 o[8];
#pragma unroll
    for (int i = 0; i < 8; i++) o[i] = make_float4(0.f, 0.f, 0.f, 0.f);

    const float scale = 0.08838834764831845f;

    for (int t = 0; t < 33; t++) {
        const float* kbase; size_t kstride;
        if (t < 32) {
            int blk = block_offsets[b * NBLK_ + t];
            kbase = k_cache + ((size_t)blk * BSZ_ * NKV_ + n) * D_;
            kstride = (size_t)NKV_ * D_;
        } else {
            kbase = g_qkv + (size_t)b * S_ * QKVW + HID_ + (size_t)n * D_;
            kstride = QKVW;
        }
        for (int e = tid; e < 64 * 32; e += 256) {
            int w = e >> 5, ck = e & 31;
            float4 v = *(const float4*)(kbase + (size_t)w * kstride + (ck << 2));
            *(float4*)&kv_s[sw_off(w, ck)] = v;
        }
        __syncthreads();

        {
            float acc[4][4];
#pragma unroll
            for (int i = 0; i < 4; i++)
#pragma unroll
                for (int j = 0; j < 4; j++) acc[i][j] = 0.f;

#pragma unroll 4
            for (int ck = 0; ck < 32; ck++) {
                float4 qv[4], kv[4];
#pragma unroll
                for (int i = 0; i < 4; i++)
                    qv[i] = *(const float4*)&q_s[sw_off(ty * 4 + i, ck)];
#pragma unroll
                for (int j = 0; j < 4; j++)
                    kv[j] = *(const float4*)&kv_s[sw_off(tx * 4 + j, ck)];
#pragma unroll
                for (int i = 0; i < 4; i++)
#pragma unroll
                    for (int j = 0; j < 4; j++)
                        acc[i][j] += qv[i].x * kv[j].x + qv[i].y * kv[j].y
                                   + qv[i].z * kv[j].z + qv[i].w * kv[j].w;
            }
#pragma unroll
            for (int i = 0; i < 4; i++)
#pragma unroll
                for (int j = 0; j < 4; j++)
                    s_s[(ty * 4 + i) * 68 + tx * 4 + j] = acc[i][j] * scale;
        }
        __syncthreads();

        {
            int r = tid >> 2, u = tid & 3;
            int lb = t * 64;
            int pr = pos_s[r];
            float mloc = -3.0e38f;
#pragma unroll
            for (int jj = 0; jj < 16; jj++) {
                int j = u * 16 + jj;
                if (lb + j <= pr) mloc = fmaxf(mloc, s_s[r * 68 + j]);
            }
            mloc = fmaxf(mloc, __shfl_xor_sync(0xffffffffu, mloc, 1));
            mloc = fmaxf(mloc, __shfl_xor_sync(0xffffffffu, mloc, 2));
            float mnew = fmaxf(row_m[r], mloc);
            float sum = 0.f;
#pragma unroll
            for (int jj = 0; jj < 16; jj++) {
                int j = u * 16 + jj;
                float pv = 0.f;
                if (lb + j <= pr) pv = expf(s_s[r * 68 + j] - mnew);
                s_s[r * 68 + j] = pv;
                sum += pv;
            }
            sum += __shfl_xor_sync(0xffffffffu, sum, 1);
            sum += __shfl_xor_sync(0xffffffffu, sum, 2);
            if (u == 0) {
                float corr = expf(row_m[r] - mnew);
                row_c[r] = corr;
                row_l[r] = row_l[r] * corr + sum;
                row_m[r] = mnew;
            }
        }
        __syncthreads();

        const float* vbase; size_t vstride;
        if (t < 32) {
            int blk = block_offsets[b * NBLK_ + t];
            vbase = v_cache + ((size_t)blk * BSZ_ * NKV_ + n) * D_;
            vstride = (size_t)NKV_ * D_;
        } else {
            vbase = g_qkv + (size_t)b * S_ * QKVW + 2 * HID_ + (size_t)n * D_;
            vstride = QKVW;
        }
        for (int e = tid; e < 64 * 32; e += 256) {
            int w = e >> 5, ck = e & 31;
            float4 v = *(const float4*)(vbase + (size_t)w * vstride + (ck << 2));
            *(float4*)&kv_s[sw_off(w, ck)] = v;
        }
        __syncthreads();

        {
            float corr = row_c[r_pv];
#pragma unroll
            for (int i = 0; i < 8; i++) {
                o[i].x *= corr; o[i].y *= corr; o[i].z *= corr; o[i].w *= corr;
            }
#pragma unroll 2
            for (int j = 0; j < 64; j++) {
                float p = s_s[r_pv * 68 + j];
#pragma unroll
                for (int i = 0; i < 8; i++) {
                    int ck = q4 + 4 * i;
                    float4 v = *(const float4*)&kv_s[sw_off(j, ck)];
                    o[i].x += p * v.x; o[i].y += p * v.y;
                    o[i].z += p * v.z; o[i].w += p * v.w;
                }
            }
        }
        __syncthreads();
    }

    float inv_l = 1.0f / row_l[r_pv];
    float* obase = g_attn + (size_t)(b * S_ + r_pv) * HID_ + (size_t)n * D_;
#pragma unroll
    for (int i = 0; i < 8; i++) {
        int ck = q4 + 4 * i;
        float4 v = o[i];
        v.x *= inv_l; v.y *= inv_l; v.z *= inv_l; v.w *= inv_l;
        *(float4*)(obase + (ck << 2)) = v;
    }
}

// ------------------------------------------------------------------
// Launch
// ------------------------------------------------------------------
extern "C" void kernel_launch(void* const* d_in, const int* in_sizes, int n_in,
                              void* d_out, int out_size)
{
    const float* X  = (const float*)d_in[0];
    const float* kc = (const float*)d_in[1];
    const float* vc = (const float*)d_in[2];
    const float* wq = (const float*)d_in[3];
    const float* wk = (const float*)d_in[4];
    const float* wv = (const float*)d_in[5];
    const float* wo = (const float*)d_in[6];
    const int* pos  = (const int*)d_in[7];
    const int* bo   = (const int*)d_in[8];
    float* out = (float*)d_out;

    float *qkv_p, *attn_p;
    cudaGetSymbolAddress((void**)&qkv_p, g_qkv);
    cudaGetSymbolAddress((void**)&attn_p, g_attn);

    int gemm_smem = 2 * STAGE + 128;   // 65664 B
    cudaFuncSetAttribute(gemm_mma, cudaFuncAttributeMaxDynamicSharedMemorySize,
                         gemm_smem);
    int attn_smem = (8192 + 8192 + 64 * 68 + 4 * 64) * 4;  // 83968 B
    cudaFuncSetAttribute(attn_k, cudaFuncAttributeMaxDynamicSharedMemorySize,
                         attn_smem);

    // 1) fused QKV projection: [512,4096] @ [4096,12288] (mma.sync bf16x2)
    dim3 g1(QKVW / 128, T_ / 128);
    gemm_mma<<<g1, 256, gemm_smem>>>(X, wq, wk, wv, qkv_p, HID_, HID_, QKVW);

    // 2) RoPE on q and k
    rope_k<<<(T_ * 64 * 64) / 256, 256>>>(pos);

    // 3) paged causal flash attention
    attn_k<<<dim3(NH_, B_), 256, attn_smem>>>(kc, vc, pos, bo);

    // 4) output projection: [512,4096] @ [4096,4096] (mma.sync bf16x2)
    dim3 g2(HID_ / 128, T_ / 128);
    gemm_mma<<<g2, 256, gemm_smem>>>(attn_p, wo, wo, wo, out, HID_, HID_, HID_);
}

// round 5
// speedup vs baseline: 3.5194x; 1.6389x over previous
#include <cuda_runtime.h>
#include <cuda_bf16.h>
#include <math.h>
#include <stdint.h>

// Problem constants
#define B_    8
#define S_    64
#define T_    512
#define HID_  4096
#define NH_   32
#define NKV_  32
#define D_    128
#define HIST_ 2048
#define BSZ_  64
#define NBLK_ 33
#define L_    2112
#define QKVW  12288   // 3 * HID_

// Scratch (device globals: allocation-guard safe)
__device__ float g_qkv[(size_t)T_ * QKVW];    // [T][q(4096) | k(4096) | v(4096)]
__device__ float g_attn[(size_t)T_ * HID_];   // attention output, pre-Wo

// ==================================================================
// Helpers: bf16 pack/unpack + mma.sync + ldmatrix (sm_80 features,
// valid at base sm_103 target)
// ==================================================================
__device__ __forceinline__ uint32_t smem_u32(const void* p) {
    return (uint32_t)__cvta_generic_to_shared(p);
}
__device__ __forceinline__ uint32_t pack_bf2(float x0, float x1) {
    uint32_t d;
    asm("cvt.rn.bf16x2.f32 %0, %1, %2;" : "=r"(d) : "f"(x1), "f"(x0));
    return d;
}
__device__ __forceinline__ float2 unpack_bf2(uint32_t u) {
    float2 r;
    r.x = __uint_as_float(u << 16);
    r.y = __uint_as_float(u & 0xffff0000u);
    return r;
}
__device__ __forceinline__ void split4(float4 v, uint32_t* hi, uint32_t* lo) {
    uint32_t h0 = pack_bf2(v.x, v.y);
    uint32_t h1 = pack_bf2(v.z, v.w);
    float2 f0 = unpack_bf2(h0), f1 = unpack_bf2(h1);
    hi[0] = h0; hi[1] = h1;
    lo[0] = pack_bf2(v.x - f0.x, v.y - f0.y);
    lo[1] = pack_bf2(v.z - f1.x, v.w - f1.y);
}
__device__ __forceinline__ void ldsm4(uint32_t* r, uint32_t addr) {
    asm volatile("ldmatrix.sync.aligned.m8n8.x4.shared.b16 {%0,%1,%2,%3}, [%4];"
                 : "=r"(r[0]), "=r"(r[1]), "=r"(r[2]), "=r"(r[3]) : "r"(addr));
}
__device__ __forceinline__ void ldsm4t(uint32_t* r, uint32_t addr) {
    asm volatile("ldmatrix.sync.aligned.m8n8.x4.trans.shared.b16 {%0,%1,%2,%3}, [%4];"
                 : "=r"(r[0]), "=r"(r[1]), "=r"(r[2]), "=r"(r[3]) : "r"(addr));
}
__device__ __forceinline__ void mma16816(float* d, const uint32_t* a, const uint32_t* b) {
    asm volatile("mma.sync.aligned.m16n8k16.row.col.f32.bf16.bf16.f32 "
                 "{%0,%1,%2,%3}, {%4,%5,%6,%7}, {%8,%9}, {%0,%1,%2,%3};"
                 : "+f"(d[0]), "+f"(d[1]), "+f"(d[2]), "+f"(d[3])
                 : "r"(a[0]), "r"(a[1]), "r"(a[2]), "r"(a[3]),
                   "r"(b[0]), "r"(b[1]));
}

// ==================================================================
// bf16x2-split GEMM on mma.sync (unchanged from R4 passing kernel).
// ==================================================================
#define BKC 32
#define NCH (HID_ / BKC)      // 128
#define TSTAGE 8192           // one tile: 128 * 64 B
#define STAGE  (4 * TSTAGE)   // 32 KB per stage

__global__ __launch_bounds__(256, 1)
void gemm_mma(const float* __restrict__ A,
              const float* __restrict__ B0, const float* __restrict__ B1,
              const float* __restrict__ B2,
              float* __restrict__ C, int K, int Nper, int Ntot)
{
    extern __shared__ char dynsm[];
    uint32_t sraw = smem_u32(dynsm);
    char* sm = dynsm + (((sraw + 127u) & ~127u) - sraw);
    uint32_t smb = smem_u32(sm);

    int tid = threadIdx.x, lane = tid & 31, wid = tid >> 5;
    int m0 = blockIdx.y * 128, col0 = blockIdx.x * 128;

    const float* Bp; int nloc;
    if (col0 < Nper)          { Bp = B0; nloc = col0; }
    else if (col0 < 2 * Nper) { Bp = B1; nloc = col0 - Nper; }
    else                      { Bp = B2; nloc = col0 - 2 * Nper; }
    size_t NperS = (size_t)Nper;

    int rA = tid >> 1, halfA = tid & 1;
    const float* Aptr = A + (size_t)(m0 + rA) * K + halfA * 16;
    int nB = tid & 127, kg = tid >> 7;
    const float* Bptr = Bp + nloc + nB;

    int rxA = (rA >> 1) & 3;
    int sA_off0 = rA * 64 + (((halfA * 2 + 0) ^ rxA) << 4);
    int sA_off1 = rA * 64 + (((halfA * 2 + 1) ^ rxA) << 4);
    int rxB = (nB >> 1) & 3;
    int sB_off0 = nB * 64 + (((kg + 0) ^ rxB) << 4);
    int sB_off1 = nB * 64 + (((kg + 2) ^ rxB) << 4);

    int wm = wid & 1, wn = wid >> 1;
    int aRow = wm * 64 + ((lane >> 3) & 1) * 8 + (lane & 7);
    int aCh  = (lane >> 4) & 1;
    int aRX  = (aRow >> 1) & 3;
    uint32_t aOff = (uint32_t)(aRow * 64);
    int nbRow = wn * 32 + ((lane >> 4) & 1) * 8 + (lane & 7);
    int bCh   = (lane >> 3) & 1;
    int bRX   = (nbRow >> 1) & 3;
    uint32_t nbOff = (uint32_t)(nbRow * 64);

    float acc[4][4][4];
#pragma unroll
    for (int i = 0; i < 4; i++)
#pragma unroll
        for (int j = 0; j < 4; j++)
#pragma unroll
            for (int e = 0; e < 4; e++) acc[i][j][e] = 0.f;

    float4 pa[4];
    float  pb[16];

    {
        const float* ap = Aptr;
#pragma unroll
        for (int q = 0; q < 4; q++) pa[q] = *(const float4*)(ap + q * 4);
        const float* bp = Bptr + (size_t)(kg * 8) * NperS;
#pragma unroll
        for (int j = 0; j < 8; j++) {
            pb[j]     = bp[(size_t)j * NperS];
            pb[8 + j] = bp[(size_t)(j + 16) * NperS];
        }
    }

    for (int c = 0; c < NCH; c++) {
        int bufOff = (c & 1) * STAGE;
        char* base = sm + bufOff;

        {
            uint32_t h[8], l[8];
#pragma unroll
            for (int q = 0; q < 4; q++) split4(pa[q], h + 2 * q, l + 2 * q);
            *(uint4*)(base + sA_off0)          = make_uint4(h[0], h[1], h[2], h[3]);
            *(uint4*)(base + sA_off1)          = make_uint4(h[4], h[5], h[6], h[7]);
            *(uint4*)(base + TSTAGE + sA_off0) = make_uint4(l[0], l[1], l[2], l[3]);
            *(uint4*)(base + TSTAGE + sA_off1) = make_uint4(l[4], l[5], l[6], l[7]);

            uint32_t bh[4], bl[4];
#pragma unroll
            for (int q = 0; q < 4; q++) {
                bh[q] = pack_bf2(pb[2 * q], pb[2 * q + 1]);
                float2 f = unpack_bf2(bh[q]);
                bl[q] = pack_bf2(pb[2 * q] - f.x, pb[2 * q + 1] - f.y);
            }
            *(uint4*)(base + 2 * TSTAGE + sB_off0) = make_uint4(bh[0], bh[1], bh[2], bh[3]);
            *(uint4*)(base + 3 * TSTAGE + sB_off0) = make_uint4(bl[0], bl[1], bl[2], bl[3]);
#pragma unroll
            for (int q = 0; q < 4; q++) {
                bh[q] = pack_bf2(pb[8 + 2 * q], pb[9 + 2 * q]);
                float2 f = unpack_bf2(bh[q]);
                bl[q] = pack_bf2(pb[8 + 2 * q] - f.x, pb[9 + 2 * q] - f.y);
            }
            *(uint4*)(base + 2 * TSTAGE + sB_off1) = make_uint4(bh[0], bh[1], bh[2], bh[3]);
            *(uint4*)(base + 3 * TSTAGE + sB_off1) = make_uint4(bl[0], bl[1], bl[2], bl[3]);
        }
        __syncthreads();

        if (c + 1 < NCH) {
            const float* ap = Aptr + (c + 1) * BKC;
#pragma unroll
            for (int q = 0; q < 4; q++) pa[q] = *(const float4*)(ap + q * 4);
            const float* bp = Bptr + (size_t)((c + 1) * BKC + kg * 8) * NperS;
#pragma unroll
            for (int j = 0; j < 8; j++) {
                pb[j]     = bp[(size_t)j * NperS];
                pb[8 + j] = bp[(size_t)(j + 16) * NperS];
            }
        }

        uint32_t stageA = smb + bufOff;
        uint32_t stageB = smb + bufOff + 2 * TSTAGE;
#pragma unroll
        for (int s = 0; s < 2; s++) {
            uint32_t bfh[4][2], bfl[4][2];
#pragma unroll
            for (int half = 0; half < 2; half++) {
                uint32_t addr = stageB + half * 1024 + nbOff
                              + ((((s * 2) + bCh) ^ bRX) << 4);
                uint32_t r[4];
                ldsm4(r, addr);
                bfh[half * 2][0] = r[0]; bfh[half * 2][1] = r[1];
                bfh[half * 2 + 1][0] = r[2]; bfh[half * 2 + 1][1] = r[3];
                ldsm4(r, addr + TSTAGE);
                bfl[half * 2][0] = r[0]; bfl[half * 2][1] = r[1];
                bfl[half * 2 + 1][0] = r[2]; bfl[half * 2 + 1][1] = r[3];
            }
#pragma unroll
            for (int mt = 0; mt < 4; mt++) {
                uint32_t addr = stageA + mt * 1024 + aOff
                              + ((((s * 2) + aCh) ^ aRX) << 4);
                uint32_t ah[4], al[4];
                ldsm4(ah, addr);
                ldsm4(al, addr + TSTAGE);
#pragma unroll
                for (int nt = 0; nt < 4; nt++) {
                    mma16816(acc[mt][nt], ah, bfh[nt]);
                    mma16816(acc[mt][nt], ah, bfl[nt]);
                    mma16816(acc[mt][nt], al, bfh[nt]);
                }
            }
        }
        __syncthreads();
    }

#pragma unroll
    for (int mt = 0; mt < 4; mt++) {
        int row = m0 + wm * 64 + mt * 16 + (lane >> 2);
#pragma unroll
        for (int nt = 0; nt < 4; nt++) {
            int col = col0 + wn * 32 + nt * 8 + (lane & 3) * 2;
            *(float2*)(C + (size_t)row * Ntot + col) =
                make_float2(acc[mt][nt][0], acc[mt][nt][1]);
            *(float2*)(C + (size_t)(row + 8) * Ntot + col) =
                make_float2(acc[mt][nt][2], acc[mt][nt][3]);
        }
    }
}

// ------------------------------------------------------------------
// RoPE in place on q/k of g_qkv (unchanged).
// ------------------------------------------------------------------
__global__ __launch_bounds__(256) void rope_k(const int* __restrict__ pos_ids)
{
    int idx = blockIdx.x * 256 + threadIdx.x;
    int i = idx & 63;
    int h = (idx >> 6) & 63;
    int t = idx >> 12;
    if (t >= T_) return;

    float p = (float)pos_ids[t];
    float inv = expf((float)i * (-9.210340371976184f / 64.0f));
    float ang = p * inv;
    float s, c;
    sincosf(ang, &s, &c);

    size_t base = (size_t)t * QKVW + (size_t)h * D_ + i;
    float x0 = g_qkv[base];
    float x1 = g_qkv[base + 64];
    g_qkv[base]      = x0 * c - x1 * s;
    g_qkv[base + 64] = x1 * c + x0 * s;
}

// ==================================================================
// Tensor-core flash attention (bf16x2 split, mma.sync).
// One CTA per (head, seq); 8 warps: wm=wid&3 (16 q rows),
// wn=wid>>2 (keys 32·wn for QK / dims 64·wn for PV).
// Smem rows: Q/K/V 256B (16 chunks of 16B), P 128B. Swizzle: c ^= row&7.
// ==================================================================
#define AQH 0u
#define AQL 16384u
#define AKH 32768u
#define AKL 49152u
#define AVH 65536u
#define AVL 81920u
#define ASS 98304u            // S: 64*68 fp32 = 17408 B
#define APH 115712u
#define APL 123904u
#define AST 132096u           // stats: 4*64*4 = 1024 B
#define ATTN_SMEM 133120

__global__ __launch_bounds__(256, 1) void attn_tc(
    const float* __restrict__ k_cache, const float* __restrict__ v_cache,
    const int* __restrict__ pos_ids, const int* __restrict__ block_offsets)
{
    extern __shared__ char smc[];
    uint32_t smb = smem_u32(smc);
    float* s_s   = (float*)(smc + ASS);
    float* row_m = (float*)(smc + AST);
    float* row_l = row_m + 64;
    float* row_c = row_l + 64;
    int*   pos_s = (int*)(row_c + 64);

    int n = blockIdx.x, b = blockIdx.y;
    int tid = threadIdx.x, lane = tid & 31, wid = tid >> 5;
    int wm = wid & 3, wn = wid >> 2;

    // ---- load Q (rope'd fp32) -> bf16 hi/lo swizzled smem ----
    const float* qbase = g_qkv + (size_t)b * S_ * QKVW + (size_t)n * D_;
#pragma unroll
    for (int i = 0; i < 8; i++) {
        int e = i * 256 + tid;
        int row = e >> 5, q = e & 31;
        float4 v = *(const float4*)(qbase + (size_t)row * QKVW + q * 4);
        uint32_t h[2], l[2];
        split4(v, h, l);
        int off = row * 256 + (((q >> 1) ^ (row & 7)) << 4) + (q & 1) * 8;
        *(uint2*)(smc + AQH + off) = make_uint2(h[0], h[1]);
        *(uint2*)(smc + AQL + off) = make_uint2(l[0], l[1]);
    }
    if (tid < 64) {
        row_m[tid] = -3.0e38f;
        row_l[tid] = 0.f;
        pos_s[tid] = pos_ids[b * S_ + tid];
    }
    __syncthreads();

    float accO[8][4];
#pragma unroll
    for (int i = 0; i < 8; i++)
#pragma unroll
        for (int e = 0; e < 4; e++) accO[i][e] = 0.f;

    const float scale = 0.08838834764831845f;  // 1/sqrt(128)

    int arow  = wm * 16 + ((lane >> 3) & 1) * 8 + (lane & 7);
    int brow0 = wn * 32 + ((lane >> 4) & 1) * 8 + (lane & 7);
    int prow  = arow;
    int vkeyb = ((lane >> 3) & 1) * 8 + (lane & 7);
    int achq  = (lane >> 4) & 1;
    int bchq  = (lane >> 3) & 1;

    for (int t = 0; t < 33; t++) {
        // ---- phase 1: load K and V tiles -> bf16 hi/lo ----
        const float *kb, *vb; size_t kstr;
        if (t < 32) {
            int blk = block_offsets[b * NBLK_ + t];
            kb = k_cache + ((size_t)blk * BSZ_ * NKV_ + n) * D_;
            vb = v_cache + ((size_t)blk * BSZ_ * NKV_ + n) * D_;
            kstr = (size_t)NKV_ * D_;
        } else {
            kb = g_qkv + (size_t)b * S_ * QKVW + HID_ + (size_t)n * D_;
            vb = kb + HID_;
            kstr = QKVW;
        }
#pragma unroll
        for (int i = 0; i < 8; i++) {
            int e = i * 256 + tid;
            int row = e >> 5, q = e & 31;
            int off = row * 256 + (((q >> 1) ^ (row & 7)) << 4) + (q & 1) * 8;
            float4 v = *(const float4*)(kb + (size_t)row * kstr + q * 4);
            uint32_t h[2], l[2];
            split4(v, h, l);
            *(uint2*)(smc + AKH + off) = make_uint2(h[0], h[1]);
            *(uint2*)(smc + AKL + off) = make_uint2(l[0], l[1]);
            float4 w = *(const float4*)(vb + (size_t)row * kstr + q * 4);
            split4(w, h, l);
            *(uint2*)(smc + AVH + off) = make_uint2(h[0], h[1]);
            *(uint2*)(smc + AVL + off) = make_uint2(l[0], l[1]);
        }
        __syncthreads();

        // ---- phase 2: S = Q K^T (bf16x2 split) ----
        float accs[4][4];
#pragma unroll
        for (int i = 0; i < 4; i++)
#pragma unroll
            for (int e = 0; e < 4; e++) accs[i][e] = 0.f;

#pragma unroll
        for (int ks = 0; ks < 8; ks++) {
            uint32_t ah[4], al[4];
            uint32_t aaddr = smb + AQH + arow * 256
                           + (((2 * ks + achq) ^ (arow & 7)) << 4);
            ldsm4(ah, aaddr);
            ldsm4(al, aaddr + (AQL - AQH));
            uint32_t bh[4][2], bl[4][2];
#pragma unroll
            for (int half = 0; half < 2; half++) {
                int brow = brow0 + half * 16;
                uint32_t baddr = smb + AKH + brow * 256
                               + (((2 * ks + bchq) ^ (brow & 7)) << 4);
                uint32_t r[4];
                ldsm4(r, baddr);
                bh[half * 2][0] = r[0]; bh[half * 2][1] = r[1];
                bh[half * 2 + 1][0] = r[2]; bh[half * 2 + 1][1] = r[3];
                ldsm4(r, baddr + (AKL - AKH));
                bl[half * 2][0] = r[0]; bl[half * 2][1] = r[1];
                bl[half * 2 + 1][0] = r[2]; bl[half * 2 + 1][1] = r[3];
            }
#pragma unroll
            for (int nt = 0; nt < 4; nt++) {
                mma16816(accs[nt], ah, bh[nt]);
                mma16816(accs[nt], ah, bl[nt]);
                mma16816(accs[nt], al, bh[nt]);
            }
        }
        {
            int r0 = wm * 16 + (lane >> 2);
            int c0 = wn * 32 + (lane & 3) * 2;
#pragma unroll
            for (int nt = 0; nt < 4; nt++) {
                *(float2*)&s_s[r0 * 68 + c0 + nt * 8] =
                    make_float2(accs[nt][0] * scale, accs[nt][1] * scale);
                *(float2*)&s_s[(r0 + 8) * 68 + c0 + nt * 8] =
                    make_float2(accs[nt][2] * scale, accs[nt][3] * scale);
            }
        }
        __syncthreads();

        // ---- phase 3: online softmax + P -> bf16 hi/lo ----
        {
            int r = tid >> 2, u = tid & 3;
            int lb = t * 64, pr = pos_s[r];
            bool nm = (lb + 63 > pr);
            float p16[16];
            float mloc = -3.0e38f;
#pragma unroll
            for (int jj = 0; jj < 16; jj++) {
                int j = u * 16 + jj;
                float sv = s_s[r * 68 + j];
                p16[jj] = sv;
                if (!nm || lb + j <= pr) mloc = fmaxf(mloc, sv);
            }
            mloc = fmaxf(mloc, __shfl_xor_sync(0xffffffffu, mloc, 1));
            mloc = fmaxf(mloc, __shfl_xor_sync(0xffffffffu, mloc, 2));
            float mnew = fmaxf(row_m[r], mloc);
            float sum = 0.f;
#pragma unroll
            for (int jj = 0; jj < 16; jj++) {
                int j = u * 16 + jj;
                float pv = 0.f;
                if (!nm || lb + j <= pr) pv = expf(p16[jj] - mnew);
                p16[jj] = pv;
                sum += pv;
            }
            sum += __shfl_xor_sync(0xffffffffu, sum, 1);
            sum += __shfl_xor_sync(0xffffffffu, sum, 2);
#pragma unroll
            for (int cc = 0; cc < 2; cc++) {
                uint32_t hw[4], lw[4];
#pragma unroll
                for (int qd = 0; qd < 4; qd++) {
                    float x0 = p16[cc * 8 + qd * 2], x1 = p16[cc * 8 + qd * 2 + 1];
                    hw[qd] = pack_bf2(x0, x1);
                    float2 f = unpack_bf2(hw[qd]);
                    lw[qd] = pack_bf2(x0 - f.x, x1 - f.y);
                }
                int off = r * 128 + (((2 * u + cc) ^ (r & 7)) << 4);
                *(uint4*)(smc + APH + off) = make_uint4(hw[0], hw[1], hw[2], hw[3]);
                *(uint4*)(smc + APL + off) = make_uint4(lw[0], lw[1], lw[2], lw[3]);
            }
            if (u == 0) {
                float corr = expf(row_m[r] - mnew);
                row_c[r] = corr;
                row_l[r] = row_l[r] * corr + sum;
                row_m[r] = mnew;
            }
        }
        __syncthreads();

        // ---- phase 4: O = O*corr + P V (bf16x2 split, ldmatrix.trans V) ----
        {
            float c0f = row_c[wm * 16 + (lane >> 2)];
            float c1f = row_c[wm * 16 + (lane >> 2) + 8];
#pragma unroll
            for (int nt = 0; nt < 8; nt++) {
                accO[nt][0] *= c0f; accO[nt][1] *= c0f;
                accO[nt][2] *= c1f; accO[nt][3] *= c1f;
            }
#pragma unroll
            for (int ks = 0; ks < 4; ks++) {
                uint32_t pha[4], pla[4];
                uint32_t paddr = smb + APH + prow * 128
                               + (((2 * ks + achq) ^ (prow & 7)) << 4);
                ldsm4(pha, paddr);
                ldsm4(pla, paddr + (APL - APH));
                int key = ks * 16 + vkeyb;
#pragma unroll
                for (int pr2 = 0; pr2 < 4; pr2++) {
                    int dch = wn * 8 + pr2 * 2 + achq;
                    uint32_t vaddr = smb + AVH + key * 256
                                   + ((dch ^ (key & 7)) << 4);
                    uint32_t rh[4], rl[4];
                    ldsm4t(rh, vaddr);
                    ldsm4t(rl, vaddr + (AVL - AVH));
                    uint32_t bh0[2] = { rh[0], rh[1] }, bh1[2] = { rh[2], rh[3] };
                    uint32_t bl0[2] = { rl[0], rl[1] }, bl1[2] = { rl[2], rl[3] };
                    mma16816(accO[pr2 * 2],     pha, bh0);
                    mma16816(accO[pr2 * 2],     pha, bl0);
                    mma16816(accO[pr2 * 2],     pla, bh0);
                    mma16816(accO[pr2 * 2 + 1], pha, bh1);
                    mma16816(accO[pr2 * 2 + 1], pha, bl1);
                    mma16816(accO[pr2 * 2 + 1], pla, bh1);
                }
            }
        }
        __syncthreads();   // protect K/V/P overwrite next tile
    }

    // ---- epilogue: normalize + write g_attn ----
    int r0 = wm * 16 + (lane >> 2);
    float il0 = 1.0f / row_l[r0];
    float il1 = 1.0f / row_l[r0 + 8];
    float* ob0 = g_attn + (size_t)(b * S_ + r0) * HID_ + (size_t)n * D_
               + wn * 64 + (lane & 3) * 2;
    float* ob1 = ob0 + 8 * HID_;
#pragma unroll
    for (int nt = 0; nt < 8; nt++) {
        *(float2*)(ob0 + nt * 8) = make_float2(accO[nt][0] * il0, accO[nt][1] * il0);
        *(float2*)(ob1 + nt * 8) = make_float2(accO[nt][2] * il1, accO[nt][3] * il1);
    }
}

// ------------------------------------------------------------------
// Launch
// ------------------------------------------------------------------
extern "C" void kernel_launch(void* const* d_in, const int* in_sizes, int n_in,
                              void* d_out, int out_size)
{
    const float* X  = (const float*)d_in[0];
    const float* kc = (const float*)d_in[1];
    const float* vc = (const float*)d_in[2];
    const float* wq = (const float*)d_in[3];
    const float* wk = (const float*)d_in[4];
    const float* wv = (const float*)d_in[5];
    const float* wo = (const float*)d_in[6];
    const int* pos  = (const int*)d_in[7];
    const int* bo   = (const int*)d_in[8];
    float* out = (float*)d_out;

    float *qkv_p, *attn_p;
    cudaGetSymbolAddress((void**)&qkv_p, g_qkv);
    cudaGetSymbolAddress((void**)&attn_p, g_attn);

    int gemm_smem = 2 * STAGE + 128;   // 65664 B
    cudaFuncSetAttribute(gemm_mma, cudaFuncAttributeMaxDynamicSharedMemorySize,
                         gemm_smem);
    cudaFuncSetAttribute(attn_tc, cudaFuncAttributeMaxDynamicSharedMemorySize,
                         ATTN_SMEM);

    // 1) fused QKV projection: [512,4096] @ [4096,12288] (mma.sync bf16x2)
    dim3 g1(QKVW / 128, T_ / 128);
    gemm_mma<<<g1, 256, gemm_smem>>>(X, wq, wk, wv, qkv_p, HID_, HID_, QKVW);

    // 2) RoPE on q and k
    rope_k<<<(T_ * 64 * 64) / 256, 256>>>(pos);

    // 3) paged causal flash attention (tensor cores)
    attn_tc<<<dim3(NH_, B_), 256, ATTN_SMEM>>>(kc, vc, pos, bo);

    // 4) output projection: [512,4096] @ [4096,4096] (mma.sync bf16x2)
    dim3 g2(HID_ / 128, T_ / 128);
    gemm_mma<<<g2, 256, gemm_smem>>>(attn_p, wo, wo, wo, out, HID_, HID_, HID_);
}